// round 3
// baseline (speedup 1.0000x reference)
#include <cuda_runtime.h>
#include <cstdint>

// Packed fp32x2 add (sm_100a): one SASS instruction for 2 fp32 adds.
#define ADD_F32X2(out, a, b) \
    asm("add.rn.f32x2 %0, %1, %2;" : "=l"(out) : "l"(a), "l"(b))

constexpr int S = 512, H = 8, D = 64;
constexpr int TILE = 64;
constexpr int STR = 68;  // floats; 272B rows: 16B-aligned (LDS.128 legal), 4*tx mod 32
                         // bank start -> conflict-free 128B wavefronts.

__global__ __launch_bounds__(256, 2)
void l1attn_kernel(const float* __restrict__ q, const float* __restrict__ k,
                   float* __restrict__ out) {
    __shared__ __align__(16) float qs[TILE * STR];
    __shared__ __align__(16) float ks[TILE * STR];

    const int bh = blockIdx.z;          // b*H + h
    const int b  = bh >> 3;
    const int h  = bh & 7;
    const int i0 = blockIdx.x * TILE;
    const int j0 = blockIdx.y * TILE;
    const int tid = threadIdx.x;

    // ---- Fill smem: q tile and NEGATED k tile ----
    #pragma unroll
    for (int idx = tid; idx < TILE * (D / 2); idx += 256) {
        const int r  = idx >> 5;
        const int dv = idx & 31;
        const float2 qv = *reinterpret_cast<const float2*>(
            q + (((b * S + i0 + r) * H + h) * D) + 2 * dv);
        *reinterpret_cast<float2*>(qs + r * STR + 2 * dv) = qv;

        float2 kv = *reinterpret_cast<const float2*>(
            k + (((b * S + j0 + r) * H + h) * D) + 2 * dv);
        kv.x = -kv.x; kv.y = -kv.y;
        *reinterpret_cast<float2*>(ks + r * STR + 2 * dv) = kv;
    }
    __syncthreads();

    const int tx = tid & 15;            // i direction
    const int ty = tid >> 4;            // j direction

    const float* qbase = qs + tx * STR;
    const float* kbase = ks + ty * STR;

    unsigned long long acc[4][4];
    #pragma unroll
    for (int c = 0; c < 4; ++c)
        #pragma unroll
        for (int e = 0; e < 4; ++e) acc[c][e] = 0ull;

    // Double-buffered registers: prefetch iter n+1 while computing iter n.
    ulonglong2 qa[4], ka[4], qb[4], kb[4];

    #pragma unroll
    for (int c = 0; c < 4; ++c)
        qa[c] = *reinterpret_cast<const ulonglong2*>(qbase + 16 * c * STR);
    #pragma unroll
    for (int e = 0; e < 4; ++e)
        ka[e] = *reinterpret_cast<const ulonglong2*>(kbase + 16 * e * STR);

    #define MATH_BLOCK(Q, K)                                                \
        _Pragma("unroll")                                                   \
        for (int c = 0; c < 4; ++c)                                         \
            _Pragma("unroll")                                               \
            for (int e = 0; e < 4; ++e) {                                   \
                unsigned long long d0, d1, t;                               \
                ADD_F32X2(d0, Q[c].x, K[e].x);                              \
                d0 &= 0x7FFFFFFF7FFFFFFFull;                                \
                ADD_F32X2(t, acc[c][e], d0);                                \
                acc[c][e] = t;                                              \
                ADD_F32X2(d1, Q[c].y, K[e].y);                              \
                d1 &= 0x7FFFFFFF7FFFFFFFull;                                \
                ADD_F32X2(t, acc[c][e], d1);                                \
                acc[c][e] = t;                                              \
            }

    #pragma unroll
    for (int d4 = 0; d4 < D / 4; d4 += 2) {
        // Prefetch d4+1 into B buffers (last pair: d4+1 = 15 still valid).
        #pragma unroll
        for (int c = 0; c < 4; ++c)
            qb[c] = *reinterpret_cast<const ulonglong2*>(
                qbase + 16 * c * STR + 4 * (d4 + 1));
        #pragma unroll
        for (int e = 0; e < 4; ++e)
            kb[e] = *reinterpret_cast<const ulonglong2*>(
                kbase + 16 * e * STR + 4 * (d4 + 1));

        MATH_BLOCK(qa, ka)

        if (d4 + 2 < D / 4) {
            #pragma unroll
            for (int c = 0; c < 4; ++c)
                qa[c] = *reinterpret_cast<const ulonglong2*>(
                    qbase + 16 * c * STR + 4 * (d4 + 2));
            #pragma unroll
            for (int e = 0; e < 4; ++e)
                ka[e] = *reinterpret_cast<const ulonglong2*>(
                    kbase + 16 * e * STR + 4 * (d4 + 2));
        }

        MATH_BLOCK(qb, kb)
    }
    #undef MATH_BLOCK

    // ---- Writeback: out[bh][j][i] = -0.125 * (lo + hi) ----
    #pragma unroll
    for (int e = 0; e < 4; ++e) {
        const int j = j0 + ty + 16 * e;
        float* orow = out + ((size_t)bh * S + j) * S + i0;
        #pragma unroll
        for (int c = 0; c < 4; ++c) {
            const unsigned long long a = acc[c][e];
            const float lo = __uint_as_float((unsigned)(a & 0xFFFFFFFFu));
            const float hi = __uint_as_float((unsigned)(a >> 32));
            orow[tx + 16 * c] = -0.125f * (lo + hi);
        }
    }
}

extern "C" void kernel_launch(void* const* d_in, const int* in_sizes, int n_in,
                              void* d_out, int out_size) {
    const float* q = (const float*)d_in[0];
    const float* k = (const float*)d_in[1];
    float* out     = (float*)d_out;
    dim3 grid(S / TILE, S / TILE, 2 * H);
    l1attn_kernel<<<grid, 256>>>(q, k, out);
}